// round 4
// baseline (speedup 1.0000x reference)
#include <cuda_runtime.h>
#include <cuda_bf16.h>

// GridSample bilinear, zeros padding, align_corners=True.
// x: [8, 64, 256, 256] fp32 ; grid: [8, 256, 256, 2] fp32 (dx,dy pixel offsets)
// out: [8, 64, 256, 256] fp32
//
// Vectorized-gather: per input row one LDG.128 covers both x-corners when they
// share a 16B float4 (75% of lanes + all clamp cases); predicated scalar LDGs
// handle the straddle case. Weight placement uses p1 = cx1 & 3 so the
// left-edge clamp (cx1 == cx0, w01 != 0) hits the correct column.

#define GS_N 8
#define GS_C 64
#define GS_H 256
#define GS_W 256
#define GS_PLANE (GS_H * GS_W)   // 65536
#define GS_PLANE4 (GS_PLANE / 4) // 16384 float4s per plane

__global__ void __launch_bounds__(256, 6) gridsample_kernel(
    const float* __restrict__ x,
    const float* __restrict__ grid,
    float* __restrict__ out)
{
    const int idx = blockIdx.x * blockDim.x + threadIdx.x;   // over N*H*W

    const int wo = idx & (GS_W - 1);
    const int ho = (idx >> 8) & (GS_H - 1);
    const int n  = idx >> 16;

    const float2 g = __ldg(reinterpret_cast<const float2*>(grid) + idx);

    // Reference chain (kept for rounding fidelity).
    const float abs_x = g.x + (float)wo;
    const float abs_y = g.y + (float)ho;
    const float norm_x = abs_x * 2.0f / (float)(GS_W - 1) - 1.0f;
    const float norm_y = abs_y * 2.0f / (float)(GS_H - 1) - 1.0f;
    const float ix = (norm_x + 1.0f) * 0.5f * (float)(GS_W - 1);
    const float iy = (norm_y + 1.0f) * 0.5f * (float)(GS_H - 1);

    const float x0f = floorf(ix);
    const float y0f = floorf(iy);
    const float wx1 = ix - x0f, wx0 = 1.0f - wx1;
    const float wy1 = iy - y0f, wy0 = 1.0f - wy1;

    const int x0 = (int)x0f, x1 = x0 + 1;
    const int y0 = (int)y0f, y1 = y0 + 1;

    const bool bx0 = (x0 >= 0) & (x0 <= GS_W - 1);
    const bool bx1 = (x1 >= 0) & (x1 <= GS_W - 1);
    const bool by0 = (y0 >= 0) & (y0 <= GS_H - 1);
    const bool by1 = (y1 >= 0) & (y1 <= GS_H - 1);

    // zeros padding: zero the weight of OOB corners
    const float w00 = wy0 * wx0 * (float)(by0 & bx0);
    const float w01 = wy0 * wx1 * (float)(by0 & bx1);
    const float w10 = wy1 * wx0 * (float)(by1 & bx0);
    const float w11 = wy1 * wx1 * (float)(by1 & bx1);

    const int cx0 = min(max(x0, 0), GS_W - 1);
    const int cx1 = min(max(x1, 0), GS_W - 1);
    const int cy0 = min(max(y0, 0), GS_H - 1);
    const int cy1 = min(max(y1, 0), GS_H - 1);

    // float4-granular column of cx0; p0/p1 = positions within that float4.
    const int col4 = cx0 >> 2;
    const int p0   = cx0 & 3;
    const int p1   = cx1 & 3;
    // cx1 lives in the same float4 unless p0==3 and cx1 advanced.
    const bool straddle = ((cx1 >> 2) != col4);

    // Per-lane float4 weight vectors: wa for row cy0, wb for row cy1.
    float wa0 = 0.f, wa1 = 0.f, wa2 = 0.f, wa3 = 0.f;
    float wb0 = 0.f, wb1 = 0.f, wb2 = 0.f, wb3 = 0.f;
    if (p0 == 0) { wa0 = w00; wb0 = w10; }
    else if (p0 == 1) { wa1 = w00; wb1 = w10; }
    else if (p0 == 2) { wa2 = w00; wb2 = w10; }
    else { wa3 = w00; wb3 = w10; }
    if (!straddle) {
        // Place w01/w11 at cx1's own position: interior -> p0+1,
        // left clamp (cx1==cx0) -> p0 (correct column!),
        // right clamp -> p0 but w01==w11==0.
        if (p1 == 0) { wa0 += w01; wb0 += w11; }
        else if (p1 == 1) { wa1 += w01; wb1 += w11; }
        else if (p1 == 2) { wa2 += w01; wb2 += w11; }
        else { wa3 += w01; wb3 += w11; }
    }

    const int nbase  = n * (GS_C * GS_PLANE);
    const int obase  = nbase + ho * GS_W + wo;

    // float4 offsets into the plane for the two rows
    const int f4off0 = cy0 * (GS_W / 4) + col4;
    const int f4off1 = cy1 * (GS_W / 4) + col4;
    // scalar offsets for the straddle corner (column cx1)
    const int s01 = cy0 * GS_W + cx1;
    const int s11 = cy1 * GS_W + cx1;

    const float4* __restrict__ xp4 = reinterpret_cast<const float4*>(x) +
                                     (nbase >> 2);
    const float* __restrict__ xp = x + nbase;
    float* __restrict__ op = out + obase;

    #pragma unroll 2
    for (int c = 0; c < GS_C; ++c) {
        const float4* p4 = xp4 + c * GS_PLANE4;
        const float4 A = __ldg(p4 + f4off0);
        const float4 B = __ldg(p4 + f4off1);
        float v = A.x * wa0 + A.y * wa1 + A.z * wa2 + A.w * wa3
                + B.x * wb0 + B.y * wb1 + B.z * wb2 + B.w * wb3;
        if (straddle) {
            const float* p = xp + c * GS_PLANE;
            v += __ldg(p + s01) * w01 + __ldg(p + s11) * w11;
        }
        op[c * GS_PLANE] = v;
    }
}

extern "C" void kernel_launch(void* const* d_in, const int* in_sizes, int n_in,
                              void* d_out, int out_size)
{
    const float* x    = (const float*)d_in[0];
    const float* grid = (const float*)d_in[1];
    float* out        = (float*)d_out;

    const int total = GS_N * GS_H * GS_W;     // 524288 spatial positions
    const int threads = 256;
    const int blocks = total / threads;       // 2048 (exact)
    gridsample_kernel<<<blocks, threads>>>(x, grid, out);
}

// round 5
// speedup vs baseline: 1.3241x; 1.3241x over previous
#include <cuda_runtime.h>
#include <cuda_bf16.h>

// GridSample bilinear, zeros padding, align_corners=True.
// x: [8, 64, 256, 256] fp32 ; grid: [8, 256, 256, 2] fp32 (dx,dy pixel offsets)
// out: [8, 64, 256, 256] fp32
//
// SMEM-staged gather: each block owns (n, 16-row output band, 16 channels).
// Per channel: stage 32 input rows (halo 8) into SMEM with coalesced LDG.128,
// then bilinear-gather from SMEM (LDS delivers exact bytes; no L1 sector
// waste). Weights/corners computed once per block and reused across channels.

#define GS_N 8
#define GS_C 64
#define GS_H 256
#define GS_W 256
#define GS_PLANE (GS_H * GS_W)        // 65536
#define TILE_H 16                      // output rows per block
#define HALO 8
#define STAGE_H (TILE_H + 2 * HALO)    // 32 staged rows
#define CH_GRP 16                      // channels per block
#define THREADS 1024
#define POS_PER_THR 4                  // 16*256/1024

__global__ void __launch_bounds__(THREADS, 1) gridsample_kernel(
    const float* __restrict__ x,
    const float* __restrict__ grid,
    float* __restrict__ out)
{
    __shared__ float tile[STAGE_H * GS_W];   // 32 KB

    const int b  = blockIdx.x;               // 512 blocks
    const int cg = b & 3;                    // channel group
    const int th = (b >> 2) & 15;            // row-band tile
    const int n  = b >> 6;                   // batch
    const int row_base = th * TILE_H;
    const int chbase   = n * GS_C + cg * CH_GRP;   // plane index base
    const int tid = threadIdx.x;

    const int spatial_base = n * GS_PLANE + row_base * GS_W;

    // ---- Precompute weights + packed corner coords for this thread's 4
    //      output positions (identical arithmetic chain to the reference) ----
    float w00[POS_PER_THR], w01[POS_PER_THR], w10[POS_PER_THR], w11[POS_PER_THR];
    int   pk[POS_PER_THR];   // (s0<<26)|(s1<<20)|(cx0<<8)|cx1

    #pragma unroll
    for (int k = 0; k < POS_PER_THR; ++k) {
        const int p  = tid + k * THREADS;    // 0..4095 within the band
        const int px = p & (GS_W - 1);
        const int py = p >> 8;
        const int ho = row_base + py;
        const int wo = px;

        const float2 g = __ldg(reinterpret_cast<const float2*>(grid) +
                               (spatial_base + p));

        const float abs_x = g.x + (float)wo;
        const float abs_y = g.y + (float)ho;
        const float norm_x = abs_x * 2.0f / (float)(GS_W - 1) - 1.0f;
        const float norm_y = abs_y * 2.0f / (float)(GS_H - 1) - 1.0f;
        const float ix = (norm_x + 1.0f) * 0.5f * (float)(GS_W - 1);
        const float iy = (norm_y + 1.0f) * 0.5f * (float)(GS_H - 1);

        const float x0f = floorf(ix);
        const float y0f = floorf(iy);
        const float wx1 = ix - x0f, wx0 = 1.0f - wx1;
        const float wy1 = iy - y0f, wy0 = 1.0f - wy1;

        const int x0 = (int)x0f, x1 = x0 + 1;
        const int y0 = (int)y0f, y1 = y0 + 1;

        const bool bx0 = (x0 >= 0) & (x0 <= GS_W - 1);
        const bool bx1 = (x1 >= 0) & (x1 <= GS_W - 1);
        const bool by0 = (y0 >= 0) & (y0 <= GS_H - 1);
        const bool by1 = (y1 >= 0) & (y1 <= GS_H - 1);

        w00[k] = wy0 * wx0 * (float)(by0 & bx0);
        w01[k] = wy0 * wx1 * (float)(by0 & bx1);
        w10[k] = wy1 * wx0 * (float)(by1 & bx0);
        w11[k] = wy1 * wx1 * (float)(by1 & bx1);

        const int cx0 = min(max(x0, 0), GS_W - 1);
        const int cx1 = min(max(x1, 0), GS_W - 1);
        const int cy0 = min(max(y0, 0), GS_H - 1);
        const int cy1 = min(max(y1, 0), GS_H - 1);

        // staged-slot indices: slot s holds global row clamp(row_base-8+s).
        // s = cy - row_base + 8 maps to exactly row cy (content clamp makes
        // the duplicated edge slots correct too). Safety-clamp to [0,31].
        const int s0 = min(max(cy0 - row_base + HALO, 0), STAGE_H - 1);
        const int s1 = min(max(cy1 - row_base + HALO, 0), STAGE_H - 1);

        pk[k] = (s0 << 26) | (s1 << 20) | (cx0 << 8) | cx1;
    }

    const float4* __restrict__ x4 = reinterpret_cast<const float4*>(x);
    float4* __restrict__ t4 = reinterpret_cast<float4*>(tile);

    // ---- Channel loop ----
    for (int ch = 0; ch < CH_GRP; ++ch) {
        const int plane = chbase + ch;

        __syncthreads();   // previous gathers done before restage

        // Stage 32 rows x 256 cols = 2048 float4s, 2 per thread, coalesced.
        #pragma unroll
        for (int i = tid; i < STAGE_H * (GS_W / 4); i += THREADS) {
            const int r  = i >> 6;            // 64 float4 per row
            const int c4 = i & 63;
            const int gy = min(max(row_base - HALO + r, 0), GS_H - 1);
            t4[i] = __ldg(x4 + plane * (GS_PLANE / 4) + gy * (GS_W / 4) + c4);
        }

        __syncthreads();

        const int obase = plane * GS_PLANE + row_base * GS_W;

        #pragma unroll
        for (int k = 0; k < POS_PER_THR; ++k) {
            const int pkk = pk[k];
            const int r0  = (pkk >> 26) << 8;          // s0 * 256
            const int r1  = ((pkk >> 20) & 63) << 8;   // s1 * 256
            const int cx0 = (pkk >> 8) & 255;
            const int cx1 = pkk & 255;
            const float v = tile[r0 + cx0] * w00[k] + tile[r0 + cx1] * w01[k]
                          + tile[r1 + cx0] * w10[k] + tile[r1 + cx1] * w11[k];
            out[obase + tid + k * THREADS] = v;
        }
    }
}

extern "C" void kernel_launch(void* const* d_in, const int* in_sizes, int n_in,
                              void* d_out, int out_size)
{
    const float* x    = (const float*)d_in[0];
    const float* grid = (const float*)d_in[1];
    float* out        = (float*)d_out;

    const int blocks = GS_N * (GS_H / TILE_H) * (GS_C / CH_GRP);  // 512
    gridsample_kernel<<<blocks, THREADS>>>(x, grid, out);
}

// round 6
// speedup vs baseline: 1.5558x; 1.1750x over previous
#include <cuda_runtime.h>
#include <cuda_bf16.h>
#include <cstdint>

// GridSample bilinear, zeros padding, align_corners=True.
// x: [8, 64, 256, 256] fp32 ; grid: [8, 256, 256, 2] fp32 (dx,dy pixel offsets)
// out: [8, 64, 256, 256] fp32
//
// SMEM-staged gather with cp.async double buffering: each block owns
// (n, 16-row output band, 16 channels). Channel ch+1 is staged via cp.async.cg
// into buf[(ch+1)&1] while channel ch is gathered from buf[ch&1] -> staging
// DRAM latency fully hidden behind the gather phase.

#define GS_N 8
#define GS_C 64
#define GS_H 256
#define GS_W 256
#define GS_PLANE (GS_H * GS_W)        // 65536
#define TILE_H 16                      // output rows per block
#define HALO 8
#define STAGE_H (TILE_H + 2 * HALO)    // 32 staged rows
#define STAGE_F4 (STAGE_H * (GS_W / 4))  // 2048 float4 per buffer
#define CH_GRP 16                      // channels per block
#define THREADS 1024
#define POS_PER_THR 4                  // 16*256/1024
#define SMEM_BYTES (2 * STAGE_H * GS_W * 4)   // 65536

__device__ __forceinline__ void cp_async16(uint32_t smem_addr, const void* gptr) {
    asm volatile("cp.async.cg.shared.global [%0], [%1], 16;\n"
                 :: "r"(smem_addr), "l"(gptr));
}
__device__ __forceinline__ void cp_commit() {
    asm volatile("cp.async.commit_group;\n");
}
template <int N>
__device__ __forceinline__ void cp_wait() {
    asm volatile("cp.async.wait_group %0;\n" :: "n"(N));
}

__global__ void __launch_bounds__(THREADS, 1) gridsample_kernel(
    const float* __restrict__ x,
    const float* __restrict__ grid,
    float* __restrict__ out)
{
    extern __shared__ float tile[];   // 2 buffers x 8192 floats

    const int b  = blockIdx.x;               // 512 blocks
    const int cg = b & 3;                    // channel group
    const int th = (b >> 2) & 15;            // row-band tile
    const int n  = b >> 6;                   // batch
    const int row_base = th * TILE_H;
    const int chbase   = n * GS_C + cg * CH_GRP;   // plane index base
    const int tid = threadIdx.x;

    const int spatial_base = n * GS_PLANE + row_base * GS_W;

    // ---- Precompute weights + packed corner coords for this thread's 4
    //      output positions (identical arithmetic chain to the reference) ----
    float w00[POS_PER_THR], w01[POS_PER_THR], w10[POS_PER_THR], w11[POS_PER_THR];
    int   pk[POS_PER_THR];   // (s0<<26)|(s1<<20)|(cx0<<8)|cx1

    #pragma unroll
    for (int k = 0; k < POS_PER_THR; ++k) {
        const int p  = tid + k * THREADS;    // 0..4095 within the band
        const int wo = p & (GS_W - 1);
        const int ho = row_base + (p >> 8);

        const float2 g = __ldg(reinterpret_cast<const float2*>(grid) +
                               (spatial_base + p));

        const float abs_x = g.x + (float)wo;
        const float abs_y = g.y + (float)ho;
        const float norm_x = abs_x * 2.0f / (float)(GS_W - 1) - 1.0f;
        const float norm_y = abs_y * 2.0f / (float)(GS_H - 1) - 1.0f;
        const float ix = (norm_x + 1.0f) * 0.5f * (float)(GS_W - 1);
        const float iy = (norm_y + 1.0f) * 0.5f * (float)(GS_H - 1);

        const float x0f = floorf(ix);
        const float y0f = floorf(iy);
        const float wx1 = ix - x0f, wx0 = 1.0f - wx1;
        const float wy1 = iy - y0f, wy0 = 1.0f - wy1;

        const int x0 = (int)x0f, x1 = x0 + 1;
        const int y0 = (int)y0f, y1 = y0 + 1;

        const bool bx0 = (x0 >= 0) & (x0 <= GS_W - 1);
        const bool bx1 = (x1 >= 0) & (x1 <= GS_W - 1);
        const bool by0 = (y0 >= 0) & (y0 <= GS_H - 1);
        const bool by1 = (y1 >= 0) & (y1 <= GS_H - 1);

        w00[k] = wy0 * wx0 * (float)(by0 & bx0);
        w01[k] = wy0 * wx1 * (float)(by0 & bx1);
        w10[k] = wy1 * wx0 * (float)(by1 & bx0);
        w11[k] = wy1 * wx1 * (float)(by1 & bx1);

        const int cx0 = min(max(x0, 0), GS_W - 1);
        const int cx1 = min(max(x1, 0), GS_W - 1);
        const int cy0 = min(max(y0, 0), GS_H - 1);
        const int cy1 = min(max(y1, 0), GS_H - 1);

        // staged-slot index: slot s holds global row clamp(row_base-8+s);
        // s = cy - row_base + 8 (safety-clamped; content clamp makes edge
        // slots hold the duplicated edge row, so it stays correct).
        const int s0 = min(max(cy0 - row_base + HALO, 0), STAGE_H - 1);
        const int s1 = min(max(cy1 - row_base + HALO, 0), STAGE_H - 1);

        pk[k] = (s0 << 26) | (s1 << 20) | (cx0 << 8) | cx1;
    }

    const float4* __restrict__ x4 = reinterpret_cast<const float4*>(x);
    const uint32_t smem_base =
        static_cast<uint32_t>(__cvta_generic_to_shared(tile));

    // Per-thread staged float4 slots: i0 = tid, i1 = tid + 1024.
    // Precompute the (clamped-row) global float4 offsets within a plane.
    int goff[2];
    #pragma unroll
    for (int k = 0; k < 2; ++k) {
        const int i  = tid + k * THREADS;
        const int r  = i >> 6;                // 64 float4 per row
        const int c4 = i & 63;
        const int gy = min(max(row_base - HALO + r, 0), GS_H - 1);
        goff[k] = gy * (GS_W / 4) + c4;
    }

    // ---- Prologue: stage channel 0 into buffer 0 ----
    {
        const int plane = chbase;
        #pragma unroll
        for (int k = 0; k < 2; ++k) {
            const int i = tid + k * THREADS;
            cp_async16(smem_base + (uint32_t)i * 16u,
                       x4 + plane * (GS_PLANE / 4) + goff[k]);
        }
        cp_commit();
    }

    // ---- Channel loop, double buffered ----
    for (int ch = 0; ch < CH_GRP; ++ch) {
        const int cur = ch & 1;

        // Issue stage for ch+1 into the other buffer (gathered 2 iters ago;
        // end-of-previous-iteration barrier protects it).
        if (ch + 1 < CH_GRP) {
            const int plane = chbase + ch + 1;
            const uint32_t dst = smem_base + (uint32_t)(1 - cur) * (STAGE_F4 * 16u);
            #pragma unroll
            for (int k = 0; k < 2; ++k) {
                const int i = tid + k * THREADS;
                cp_async16(dst + (uint32_t)i * 16u,
                           x4 + plane * (GS_PLANE / 4) + goff[k]);
            }
            cp_commit();
            cp_wait<1>();    // current channel's stage complete
        } else {
            cp_wait<0>();
        }
        __syncthreads();     // all threads' stages visible

        const float* buf = tile + cur * (STAGE_F4 * 4);
        const int plane = chbase + ch;
        const int obase = plane * GS_PLANE + row_base * GS_W;

        #pragma unroll
        for (int k = 0; k < POS_PER_THR; ++k) {
            const int pkk = pk[k];
            const int r0  = (pkk >> 26) << 8;          // s0 * 256
            const int r1  = ((pkk >> 20) & 63) << 8;   // s1 * 256
            const int cx0 = (pkk >> 8) & 255;
            const int cx1 = pkk & 255;
            const float v = buf[r0 + cx0] * w00[k] + buf[r0 + cx1] * w01[k]
                          + buf[r1 + cx0] * w10[k] + buf[r1 + cx1] * w11[k];
            out[obase + tid + k * THREADS] = v;
        }

        __syncthreads();     // gathers done before this buffer is restaged
    }
}

extern "C" void kernel_launch(void* const* d_in, const int* in_sizes, int n_in,
                              void* d_out, int out_size)
{
    const float* x    = (const float*)d_in[0];
    const float* grid = (const float*)d_in[1];
    float* out        = (float*)d_out;

    cudaFuncSetAttribute(gridsample_kernel,
                         cudaFuncAttributeMaxDynamicSharedMemorySize,
                         SMEM_BYTES);

    const int blocks = GS_N * (GS_H / TILE_H) * (GS_C / CH_GRP);  // 512
    gridsample_kernel<<<blocks, THREADS, SMEM_BYTES>>>(x, grid, out);
}

// round 8
// speedup vs baseline: 1.7671x; 1.1358x over previous
#include <cuda_runtime.h>
#include <cuda_bf16.h>
#include <cstdint>

// GridSample bilinear, zeros padding, align_corners=True.
// x: [8, 64, 256, 256] fp32 ; grid: [8, 256, 256, 2] fp32 (dx,dy pixel offsets)
// out: [8, 64, 256, 256] fp32
//
// SMEM-staged gather, triple-buffered cp.async pipeline, ONE barrier per
// channel. Block owns (n, 16-row band, 16 channels). Stage for ch+2 is issued
// while gathering ch -> ~2 gather-phases of latency cover.

#define GS_N 8
#define GS_C 64
#define GS_H 256
#define GS_W 256
#define GS_PLANE (GS_H * GS_W)        // 65536
#define TILE_H 16
#define HALO 8
#define STAGE_H (TILE_H + 2 * HALO)    // 32 staged rows
#define STAGE_F4 (STAGE_H * (GS_W / 4))  // 2048 float4 per buffer
#define NBUF 3
#define CH_GRP 16
#define THREADS 1024
#define POS_PER_THR 4
#define SMEM_BYTES (NBUF * STAGE_H * GS_W * 4)   // 98304

__device__ __forceinline__ void cp_async16(uint32_t smem_addr, const void* gptr) {
    asm volatile("cp.async.cg.shared.global [%0], [%1], 16;\n"
                 :: "r"(smem_addr), "l"(gptr));
}
__device__ __forceinline__ void cp_commit() {
    asm volatile("cp.async.commit_group;\n");
}
template <int N>
__device__ __forceinline__ void cp_wait() {
    asm volatile("cp.async.wait_group %0;\n" :: "n"(N));
}

__global__ void __launch_bounds__(THREADS, 1) gridsample_kernel(
    const float* __restrict__ x,
    const float* __restrict__ grid,
    float* __restrict__ out)
{
    extern __shared__ float tile[];   // NBUF x 8192 floats

    const int b  = blockIdx.x;               // 512 blocks
    const int cg = b & 3;                    // channel group
    const int th = (b >> 2) & 15;            // row-band tile
    const int n  = b >> 6;                   // batch
    const int row_base = th * TILE_H;
    const int chbase   = n * GS_C + cg * CH_GRP;
    const int tid = threadIdx.x;

    const float4* __restrict__ x4 = reinterpret_cast<const float4*>(x);
    const uint32_t smem_base =
        static_cast<uint32_t>(__cvta_generic_to_shared(tile));

    // Per-thread staged float4 slots (clamped-row global offsets in a plane).
    int goff[2];
    #pragma unroll
    for (int k = 0; k < 2; ++k) {
        const int i  = tid + k * THREADS;
        const int r  = i >> 6;                // 64 float4 per row
        const int c4 = i & 63;
        const int gy = min(max(row_base - HALO + r, 0), GS_H - 1);
        goff[k] = gy * (GS_W / 4) + c4;
    }

    // ---- Prologue: stage ch0 -> buf0, ch1 -> buf1 (before weight math so
    //      the grid-load latency overlaps the staging) ----
    #pragma unroll
    for (int c = 0; c < 2; ++c) {
        const int plane = chbase + c;
        const uint32_t dst = smem_base + (uint32_t)c * (STAGE_F4 * 16u);
        #pragma unroll
        for (int k = 0; k < 2; ++k) {
            const int i = tid + k * THREADS;
            cp_async16(dst + (uint32_t)i * 16u,
                       x4 + plane * (GS_PLANE / 4) + goff[k]);
        }
        cp_commit();
    }

    // ---- Weights + packed corner coords for this thread's 4 positions ----
    const int spatial_base = n * GS_PLANE + row_base * GS_W;
    float w00[POS_PER_THR], w01[POS_PER_THR], w10[POS_PER_THR], w11[POS_PER_THR];
    int   pk[POS_PER_THR];   // (s0<<26)|(s1<<20)|(cx0<<8)|cx1

    #pragma unroll
    for (int k = 0; k < POS_PER_THR; ++k) {
        const int p  = tid + k * THREADS;
        const int wo = p & (GS_W - 1);
        const int ho = row_base + (p >> 8);

        const float2 g = __ldg(reinterpret_cast<const float2*>(grid) +
                               (spatial_base + p));

        const float abs_x = g.x + (float)wo;
        const float abs_y = g.y + (float)ho;
        const float norm_x = abs_x * 2.0f / (float)(GS_W - 1) - 1.0f;
        const float norm_y = abs_y * 2.0f / (float)(GS_H - 1) - 1.0f;
        const float ix = (norm_x + 1.0f) * 0.5f * (float)(GS_W - 1);
        const float iy = (norm_y + 1.0f) * 0.5f * (float)(GS_H - 1);

        const float x0f = floorf(ix);
        const float y0f = floorf(iy);
        const float wx1 = ix - x0f, wx0 = 1.0f - wx1;
        const float wy1 = iy - y0f, wy0 = 1.0f - wy1;

        const int x0 = (int)x0f, x1 = x0 + 1;
        const int y0 = (int)y0f, y1 = y0 + 1;

        const bool bx0 = (x0 >= 0) & (x0 <= GS_W - 1);
        const bool bx1 = (x1 >= 0) & (x1 <= GS_W - 1);
        const bool by0 = (y0 >= 0) & (y0 <= GS_H - 1);
        const bool by1 = (y1 >= 0) & (y1 <= GS_H - 1);

        w00[k] = wy0 * wx0 * (float)(by0 & bx0);
        w01[k] = wy0 * wx1 * (float)(by0 & bx1);
        w10[k] = wy1 * wx0 * (float)(by1 & bx0);
        w11[k] = wy1 * wx1 * (float)(by1 & bx1);

        const int cx0 = min(max(x0, 0), GS_W - 1);
        const int cx1 = min(max(x1, 0), GS_W - 1);
        const int cy0 = min(max(y0, 0), GS_H - 1);
        const int cy1 = min(max(y1, 0), GS_H - 1);

        const int s0 = min(max(cy0 - row_base + HALO, 0), STAGE_H - 1);
        const int s1 = min(max(cy1 - row_base + HALO, 0), STAGE_H - 1);

        pk[k] = (s0 << 26) | (s1 << 20) | (cx0 << 8) | cx1;
    }

    // ---- Channel loop: 1 barrier per channel, depth-3 buffers ----
    for (int ch = 0; ch < CH_GRP; ++ch) {
        // Stage for ch complete (the group for ch+1 may remain in flight).
        if (ch < CH_GRP - 1) cp_wait<1>(); else cp_wait<0>();

        // Single barrier: makes ch's staged data visible to all threads AND
        // guarantees all gathers of ch-1 are done (WAR for re-staging
        // buffer (ch+2)%3 == (ch-1)%3).
        __syncthreads();

        // Issue stage for ch+2.
        if (ch + 2 < CH_GRP) {
            const int plane = chbase + ch + 2;
            const uint32_t dst = smem_base +
                (uint32_t)((ch + 2) % NBUF) * (STAGE_F4 * 16u);
            #pragma unroll
            for (int k = 0; k < 2; ++k) {
                const int i = tid + k * THREADS;
                cp_async16(dst + (uint32_t)i * 16u,
                           x4 + plane * (GS_PLANE / 4) + goff[k]);
            }
            cp_commit();
        }

        // Gather ch from buf[ch % 3].
        const float* buf = tile + (ch % NBUF) * (STAGE_F4 * 4);
        const int plane = chbase + ch;
        const int obase = plane * GS_PLANE + row_base * GS_W;

        #pragma unroll
        for (int k = 0; k < POS_PER_THR; ++k) {
            const int pkk = pk[k];
            const int r0  = (pkk >> 26) << 8;          // s0 * 256
            const int r1  = ((pkk >> 20) & 63) << 8;   // s1 * 256
            const int cx0 = (pkk >> 8) & 255;
            const int cx1 = pkk & 255;
            const float v = buf[r0 + cx0] * w00[k] + buf[r0 + cx1] * w01[k]
                          + buf[r1 + cx0] * w10[k] + buf[r1 + cx1] * w11[k];
            __stcs(&out[obase + tid + k * THREADS], v);   // streaming store
        }
    }
}

extern "C" void kernel_launch(void* const* d_in, const int* in_sizes, int n_in,
                              void* d_out, int out_size)
{
    const float* x    = (const float*)d_in[0];
    const float* grid = (const float*)d_in[1];
    float* out        = (float*)d_out;

    cudaFuncSetAttribute(gridsample_kernel,
                         cudaFuncAttributeMaxDynamicSharedMemorySize,
                         SMEM_BYTES);

    const int blocks = GS_N * (GS_H / TILE_H) * (GS_C / CH_GRP);  // 512
    gridsample_kernel<<<blocks, THREADS, SMEM_BYTES>>>(x, grid, out);
}

// round 9
// speedup vs baseline: 2.0624x; 1.1671x over previous
#include <cuda_runtime.h>
#include <cuda_bf16.h>
#include <cstdint>

// GridSample bilinear, zeros padding, align_corners=True.
// x: [8, 64, 256, 256] fp32 ; grid: [8, 256, 256, 2] fp32 (dx,dy pixel offsets)
// out: [8, 64, 256, 256] fp32
//
// SMEM-staged gather, triple-buffered cp.async pipeline, one barrier per
// channel, 512-thread blocks (8-row band x 16 channels) so TWO independent
// pipelines co-reside per SM -> one block's barrier/wait bubbles are covered
// by the other block's warps.

#define GS_N 8
#define GS_C 64
#define GS_H 256
#define GS_W 256
#define GS_PLANE (GS_H * GS_W)          // 65536
#define TILE_H 8
#define HALO 8
#define STAGE_H (TILE_H + 2 * HALO)      // 24 staged rows
#define STAGE_F4 (STAGE_H * (GS_W / 4))  // 1536 float4 per buffer
#define NBUF 3
#define CH_GRP 16
#define THREADS 512
#define POS_PER_THR 4                    // 8*256/512
#define SLOTS 3                          // 1536/512 stage float4s per thread
#define SMEM_BYTES (NBUF * STAGE_H * GS_W * 4)   // 73728

__device__ __forceinline__ void cp_async16(uint32_t smem_addr, const void* gptr) {
    asm volatile("cp.async.cg.shared.global [%0], [%1], 16;\n"
                 :: "r"(smem_addr), "l"(gptr));
}
__device__ __forceinline__ void cp_commit() {
    asm volatile("cp.async.commit_group;\n");
}
template <int N>
__device__ __forceinline__ void cp_wait() {
    asm volatile("cp.async.wait_group %0;\n" :: "n"(N));
}

__global__ void __launch_bounds__(THREADS, 2) gridsample_kernel(
    const float* __restrict__ x,
    const float* __restrict__ grid,
    float* __restrict__ out)
{
    extern __shared__ float tile[];   // NBUF x 6144 floats

    const int b  = blockIdx.x;               // 1024 blocks
    const int cg = b & 3;                    // channel group (16 ch)
    const int th = (b >> 2) & 31;            // row-band tile (8 rows)
    const int n  = b >> 7;                   // batch
    const int row_base = th * TILE_H;
    const int chbase   = n * GS_C + cg * CH_GRP;
    const int tid = threadIdx.x;

    const float4* __restrict__ x4 = reinterpret_cast<const float4*>(x);
    const uint32_t smem_base =
        static_cast<uint32_t>(__cvta_generic_to_shared(tile));

    // Per-thread staged float4 slots (clamped-row global offsets in a plane).
    int goff[SLOTS];
    #pragma unroll
    for (int k = 0; k < SLOTS; ++k) {
        const int i  = tid + k * THREADS;
        const int r  = i >> 6;                // 64 float4 per row
        const int c4 = i & 63;
        const int gy = min(max(row_base - HALO + r, 0), GS_H - 1);
        goff[k] = gy * (GS_W / 4) + c4;
    }

    // ---- Prologue: stage ch0 -> buf0, ch1 -> buf1 ----
    #pragma unroll
    for (int c = 0; c < 2; ++c) {
        const int plane = chbase + c;
        const uint32_t dst = smem_base + (uint32_t)c * (STAGE_F4 * 16u);
        #pragma unroll
        for (int k = 0; k < SLOTS; ++k) {
            const int i = tid + k * THREADS;
            cp_async16(dst + (uint32_t)i * 16u,
                       x4 + plane * (GS_PLANE / 4) + goff[k]);
        }
        cp_commit();
    }

    // ---- Weights + packed corner coords for this thread's 4 positions ----
    const int spatial_base = n * GS_PLANE + row_base * GS_W;
    float w00[POS_PER_THR], w01[POS_PER_THR], w10[POS_PER_THR], w11[POS_PER_THR];
    int   pk[POS_PER_THR];   // (s0<<26)|(s1<<20)|(cx0<<8)|cx1

    #pragma unroll
    for (int k = 0; k < POS_PER_THR; ++k) {
        const int p  = tid + k * THREADS;    // 0..2047 within the band
        const int wo = p & (GS_W - 1);
        const int ho = row_base + (p >> 8);

        const float2 g = __ldg(reinterpret_cast<const float2*>(grid) +
                               (spatial_base + p));

        const float abs_x = g.x + (float)wo;
        const float abs_y = g.y + (float)ho;
        const float norm_x = abs_x * 2.0f / (float)(GS_W - 1) - 1.0f;
        const float norm_y = abs_y * 2.0f / (float)(GS_H - 1) - 1.0f;
        const float ix = (norm_x + 1.0f) * 0.5f * (float)(GS_W - 1);
        const float iy = (norm_y + 1.0f) * 0.5f * (float)(GS_H - 1);

        const float x0f = floorf(ix);
        const float y0f = floorf(iy);
        const float wx1 = ix - x0f, wx0 = 1.0f - wx1;
        const float wy1 = iy - y0f, wy0 = 1.0f - wy1;

        const int x0 = (int)x0f, x1 = x0 + 1;
        const int y0 = (int)y0f, y1 = y0 + 1;

        const bool bx0 = (x0 >= 0) & (x0 <= GS_W - 1);
        const bool bx1 = (x1 >= 0) & (x1 <= GS_W - 1);
        const bool by0 = (y0 >= 0) & (y0 <= GS_H - 1);
        const bool by1 = (y1 >= 0) & (y1 <= GS_H - 1);

        w00[k] = wy0 * wx0 * (float)(by0 & bx0);
        w01[k] = wy0 * wx1 * (float)(by0 & bx1);
        w10[k] = wy1 * wx0 * (float)(by1 & bx0);
        w11[k] = wy1 * wx1 * (float)(by1 & bx1);

        const int cx0 = min(max(x0, 0), GS_W - 1);
        const int cx1 = min(max(x1, 0), GS_W - 1);
        const int cy0 = min(max(y0, 0), GS_H - 1);
        const int cy1 = min(max(y1, 0), GS_H - 1);

        const int s0 = min(max(cy0 - row_base + HALO, 0), STAGE_H - 1);
        const int s1 = min(max(cy1 - row_base + HALO, 0), STAGE_H - 1);

        pk[k] = (s0 << 26) | (s1 << 20) | (cx0 << 8) | cx1;
    }

    // ---- Channel loop: 1 barrier per channel, depth-3 buffers ----
    for (int ch = 0; ch < CH_GRP; ++ch) {
        if (ch < CH_GRP - 1) cp_wait<1>(); else cp_wait<0>();

        // Single barrier: ch's stage visible to all + WAR guard for
        // re-staging buffer (ch+2)%3 == (ch-1)%3.
        __syncthreads();

        if (ch + 2 < CH_GRP) {
            const int plane = chbase + ch + 2;
            const uint32_t dst = smem_base +
                (uint32_t)((ch + 2) % NBUF) * (STAGE_F4 * 16u);
            #pragma unroll
            for (int k = 0; k < SLOTS; ++k) {
                const int i = tid + k * THREADS;
                cp_async16(dst + (uint32_t)i * 16u,
                           x4 + plane * (GS_PLANE / 4) + goff[k]);
            }
            cp_commit();
        }

        const float* buf = tile + (ch % NBUF) * (STAGE_F4 * 4);
        const int plane = chbase + ch;
        const int obase = plane * GS_PLANE + row_base * GS_W;

        #pragma unroll
        for (int k = 0; k < POS_PER_THR; ++k) {
            const int pkk = pk[k];
            const int r0  = (pkk >> 26) << 8;          // s0 * 256
            const int r1  = ((pkk >> 20) & 63) << 8;   // s1 * 256
            const int cx0 = (pkk >> 8) & 255;
            const int cx1 = pkk & 255;
            const float v = buf[r0 + cx0] * w00[k] + buf[r0 + cx1] * w01[k]
                          + buf[r1 + cx0] * w10[k] + buf[r1 + cx1] * w11[k];
            __stcs(&out[obase + tid + k * THREADS], v);   // streaming store
        }
    }
}

extern "C" void kernel_launch(void* const* d_in, const int* in_sizes, int n_in,
                              void* d_out, int out_size)
{
    const float* x    = (const float*)d_in[0];
    const float* grid = (const float*)d_in[1];
    float* out        = (float*)d_out;

    cudaFuncSetAttribute(gridsample_kernel,
                         cudaFuncAttributeMaxDynamicSharedMemorySize,
                         SMEM_BYTES);

    const int blocks = GS_N * (GS_H / TILE_H) * (GS_C / CH_GRP);  // 1024
    gridsample_kernel<<<blocks, THREADS, SMEM_BYTES>>>(x, grid, out);
}